// round 3
// baseline (speedup 1.0000x reference)
#include <cuda_runtime.h>
#include <cuda_bf16.h>
#include <cstdint>

// Output: [32, 4096, 1024] fp32. out[..., c] = coef if (c odd && c < 1022) else 0.
// Row = 1024 floats = 256 float4s; every float4 is (0,coef,0,coef) except the
// last float4 of each row, which is (0,coef,0,0).
//
// Single-wave persistent launch: 148 SMs x 8 blocks x 256 threads, all
// resident (26 regs, 0 smem). Grid-stride with stride = GRID*256 vec4s.
// Base index = bid*256 + tid  ==>  (index mod 256) == tid for every store,
// so only tid==255 ever writes a row-tail float4 and the store value is a
// per-thread constant. 110 unrolled stores/thread + tail iteration for the
// first 832 blocks (110*303104 + 832*256 = 33,554,432 = total vec4s).

static constexpr int       THREADS     = 256;
static constexpr int       BLOCKS      = 148 * 8;            // 1184, one wave
static constexpr long long STRIDE      = (long long)BLOCKS * THREADS; // 303,104
static constexpr int       FULL_ITERS  = 110;
static constexpr int       TAIL_BLOCKS = 832;                // blocks doing iter 110

__global__ __launch_bounds__(THREADS)
void posenc_fill_kernel(float4* __restrict__ out,
                        const float* __restrict__ coef_ptr) {
    const float coef = __ldg(coef_ptr);
    const float w3 = (threadIdx.x == THREADS - 1) ? 0.0f : coef;
    const float4 val = make_float4(0.0f, coef, 0.0f, w3);

    float4* p = out + (long long)blockIdx.x * THREADS + threadIdx.x;
#pragma unroll
    for (int k = 0; k < FULL_ITERS; ++k) {
        __stcs(p + k * STRIDE, val);   // STG.E.128 with streaming (evict-first) hint
    }
    if (blockIdx.x < TAIL_BLOCKS) {
        __stcs(p + FULL_ITERS * STRIDE, val);
    }
}

extern "C" void kernel_launch(void* const* d_in, const int* in_sizes, int n_in,
                              void* d_out, int out_size) {
    const float* coef = (const float*)d_in[n_in - 1];  // coef_param is last input
    posenc_fill_kernel<<<BLOCKS, THREADS>>>((float4*)d_out, coef);
}

// round 6
// speedup vs baseline: 1.1807x; 1.1807x over previous
#include <cuda_runtime.h>
#include <cuda_bf16.h>
#include <cstdint>

// Output: [32, 4096, 1024] fp32. out[..., c] = coef if (c odd && c < 1022) else 0.
// Row = 1024 floats = 256 float4s; all float4s are (0,coef,0,coef) except the
// last float4 of each row which is (0,coef,0,0).
//
// Round-2 structure (best: 77.8us, occ 90.5%, 26 regs): blockDim=256, each
// thread stores 16 float4s at stride 256 float4s. Block base is a multiple of
// 256 vec4s, so every store by thread t lands at within-row float4 index t:
// only tid==255 ever writes a row-tail float4 -> store value is a per-thread
// constant. Single change vs round 2: __stcs (STG.E.128 evict-first) so the
// 512MB write stream doesn't thrash L2.

static constexpr long long TOTAL_VEC4     = 32LL * 4096LL * 1024LL / 4;  // 33,554,432
static constexpr int       THREADS        = 256;
static constexpr int       VEC_PER_THREAD = 16;
static constexpr int       VEC_PER_BLOCK  = THREADS * VEC_PER_THREAD;    // 4096
static constexpr int       BLOCKS         = (int)(TOTAL_VEC4 / VEC_PER_BLOCK); // 8192

__global__ __launch_bounds__(THREADS)
void posenc_fill_kernel(float4* __restrict__ out,
                        const float* __restrict__ coef_ptr) {
    const float coef = __ldg(coef_ptr);
    const float w3 = (threadIdx.x == THREADS - 1) ? 0.0f : coef;
    const float4 val = make_float4(0.0f, coef, 0.0f, w3);

    float4* p = out + (long long)blockIdx.x * VEC_PER_BLOCK + threadIdx.x;
#pragma unroll
    for (int k = 0; k < VEC_PER_THREAD; ++k) {
        __stcs(p + k * THREADS, val);   // immediate offset k*4096B, evict-first
    }
}

extern "C" void kernel_launch(void* const* d_in, const int* in_sizes, int n_in,
                              void* d_out, int out_size) {
    const float* coef = (const float*)d_in[n_in - 1];  // coef_param is last input
    posenc_fill_kernel<<<BLOCKS, THREADS>>>((float4*)d_out, coef);
}